// round 1
// baseline (speedup 1.0000x reference)
#include <cuda_runtime.h>
#include <cuda_bf16.h>

// Problem constants (fixed by setup_inputs)
#define BB 4
#define CC 128
#define HH 512
#define WW 512
#define HWPX (HH * WW)          // 262144 pixels per image
#define NT 800                  // n_tokens
#define ML 1024                 // max_length
#define NSEG (BB * NT)          // 3200
#define NCLS 5

// Output layout (concatenated f32): tokens [B,ML,C] | labels [B,ML] | pads [B,1]
#define TOK_ELEMS ((size_t)BB * ML * CC)   // 524288
#define LAB_OFF   TOK_ELEMS
#define PAD_OFF   (TOK_ELEMS + (size_t)BB * ML)

// Scratch (static device globals — no allocation at runtime)
__device__ int   g_counts [NSEG];
__device__ int   g_cursor [NSEG];
__device__ int   g_offsets[NSEG];
__device__ int   g_hist   [NSEG * NCLS];
__device__ float g_fsorted[(size_t)BB * HWPX * CC];   // 512 MB, pixel-major rows of 128 ch

// ---------------------------------------------------------------------------
// K1: zero counters
// ---------------------------------------------------------------------------
__global__ void k1_init() {
    int i = blockIdx.x * blockDim.x + threadIdx.x;
    if (i < NSEG) { g_counts[i] = 0; g_cursor[i] = 0; }
    if (i < NSEG * NCLS) g_hist[i] = 0;
}

// ---------------------------------------------------------------------------
// K2: per-pixel stats: segment counts + class histogram
// ---------------------------------------------------------------------------
__global__ void k2_stats(const int* __restrict__ seg, const int* __restrict__ gts) {
    int n = BB * HWPX;
    for (int i = blockIdx.x * blockDim.x + threadIdx.x; i < n;
         i += gridDim.x * blockDim.x) {
        int b = i / HWPX;
        int s = seg[i] + b * NT;
        atomicAdd(&g_counts[s], 1);
        atomicAdd(&g_hist[s * NCLS + gts[i]], 1);
    }
}

// ---------------------------------------------------------------------------
// K3: exclusive prefix sum of counts -> offsets (single 1024-thread block)
// ---------------------------------------------------------------------------
__global__ void k3_scan() {
    __shared__ int sdata[1024];
    __shared__ int carry;
    int t = threadIdx.x;
    if (t == 0) carry = 0;
    __syncthreads();
    for (int base = 0; base < NSEG; base += 1024) {
        int idx = base + t;
        int v = (idx < NSEG) ? g_counts[idx] : 0;
        sdata[t] = v;
        __syncthreads();
        for (int ofs = 1; ofs < 1024; ofs <<= 1) {
            int add = (t >= ofs) ? sdata[t - ofs] : 0;
            __syncthreads();
            sdata[t] += add;
            __syncthreads();
        }
        int incl = sdata[t];
        if (idx < NSEG) g_offsets[idx] = carry + (incl - v);
        __syncthreads();
        if (t == 1023) carry += incl;
        __syncthreads();
    }
}

// ---------------------------------------------------------------------------
// K4: fused rank assignment + transpose + permuted row write.
// Block handles 64 pixels x 128 channels of one image.
//  - rank[p] = offsets[seg] + ticket (global atomic, spread over 3200 addrs)
//  - load channel-major (coalesced LDG), transpose via smem tile (pitch 132),
//  - write 512B pixel rows to g_fsorted[rank] (fully coalesced STG.128)
// ---------------------------------------------------------------------------
#define K4_PIX 64
#define K4_PITCH 132   // multiple of 4 (float4-aligned reads), +4 to break worst conflicts

__global__ __launch_bounds__(256) void k4_permute(const float* __restrict__ F,
                                                  const int* __restrict__ seg) {
    __shared__ float tile[K4_PIX * K4_PITCH];
    __shared__ int   rank[K4_PIX];

    int b  = blockIdx.y;
    int p0 = blockIdx.x * K4_PIX;
    int t  = threadIdx.x;
    int w  = t >> 5;
    int l  = t & 31;

    if (t < K4_PIX) {
        int s = seg[b * HWPX + p0 + t] + b * NT;
        rank[t] = g_offsets[s] + atomicAdd(&g_cursor[s], 1);
    }

    const float* Fb = F + (size_t)b * CC * HWPX;

    // 256 warp-tasks: task = c*2 + g ; warp covers 32 consecutive pixels of one channel
#pragma unroll
    for (int task = w; task < 256; task += 8) {
        int c = task >> 1;
        int p = ((task & 1) << 5) + l;
        tile[p * K4_PITCH + c] = Fb[(size_t)c * HWPX + p0 + p];
    }
    __syncthreads();

    // each warp writes 8 pixel rows: lane = channel quad, fully coalesced 512B
#pragma unroll
    for (int i = 0; i < 8; i++) {
        int p = i * 8 + w;
        float4 v = *(const float4*)&tile[p * K4_PITCH + 4 * l];
        *(float4*)&g_fsorted[(size_t)rank[p] * CC + 4 * l] = v;
    }
}

// ---------------------------------------------------------------------------
// K5: per-segment reduction + finalize (means, modes, padding, pads)
// grid (ML, B); 128 threads = 4 warps; warp strides rows, float4 reg accum.
// ---------------------------------------------------------------------------
__global__ __launch_bounds__(128) void k5_reduce(float* __restrict__ out) {
    int b  = blockIdx.y;
    int sl = blockIdx.x;
    int t  = threadIdx.x;
    int w  = t >> 5;
    int l  = t & 31;

    float* tok = out + ((size_t)b * ML + sl) * CC;

    if (sl >= NT) {   // padding region: zero token row + zero label
        if (t < 32) ((float4*)tok)[t] = make_float4(0.f, 0.f, 0.f, 0.f);
        if (t == 0) out[LAB_OFF + (size_t)b * ML + sl] = 0.f;
        return;
    }

    int s   = b * NT + sl;
    int off = g_offsets[s];
    int cnt = g_counts[s];

    float4 acc = make_float4(0.f, 0.f, 0.f, 0.f);
    const float* base = g_fsorted + (size_t)off * CC + 4 * l;

    int r = w;
#pragma unroll 4
    for (; r < cnt; r += 4) {
        float4 v = *(const float4*)(base + (size_t)r * CC);
        acc.x += v.x; acc.y += v.y; acc.z += v.z; acc.w += v.w;
    }

    __shared__ float4 part[4][32];
    part[w][l] = acc;
    __syncthreads();

    if (w == 0) {
        float4 a0 = part[0][l], a1 = part[1][l], a2 = part[2][l], a3 = part[3][l];
        int d = cnt > 0 ? cnt : 1;
        float inv = 1.f / (float)d;
        float4 m;
        m.x = (a0.x + a1.x + a2.x + a3.x) * inv;
        m.y = (a0.y + a1.y + a2.y + a3.y) * inv;
        m.z = (a0.z + a1.z + a2.z + a3.z) * inv;
        m.w = (a0.w + a1.w + a2.w + a3.w) * inv;
        ((float4*)tok)[l] = m;
    }

    if (t == 0) {
        int base_h = s * NCLS;
        int best = 0, bc = g_hist[base_h];
#pragma unroll
        for (int c = 1; c < NCLS; c++) {
            int h = g_hist[base_h + c];
            if (h > bc) { bc = h; best = c; }
        }
        out[LAB_OFF + (size_t)b * ML + sl] = (float)best;
        if (sl == 0) out[PAD_OFF + b] = (float)(ML - NT);
    }
}

// ---------------------------------------------------------------------------
extern "C" void kernel_launch(void* const* d_in, const int* in_sizes, int n_in,
                              void* d_out, int out_size) {
    const float* features = (const float*)d_in[0];
    const int*   gts      = (const int*)d_in[1];
    const int*   segments = (const int*)d_in[2];
    float*       out      = (float*)d_out;

    (void)in_sizes; (void)n_in; (void)out_size;

    k1_init<<<(NSEG * NCLS + 255) / 256, 256>>>();
    k2_stats<<<2048, 256>>>(segments, gts);
    k3_scan<<<1, 1024>>>();
    {
        dim3 g(HWPX / K4_PIX, BB);   // (4096, 4)
        k4_permute<<<g, 256>>>(features, segments);
    }
    {
        dim3 g(ML, BB);              // (1024, 4)
        k5_reduce<<<g, 128>>>(out);
    }
}

// round 2
// speedup vs baseline: 2.9031x; 2.9031x over previous
#include <cuda_runtime.h>
#include <cuda_bf16.h>
#include <cstdint>

// Problem constants (fixed by setup_inputs)
#define BB 4
#define CC 128
#define HH 512
#define WW 512
#define HWPX (HH * WW)          // 262144 pixels per image
#define NT 800                  // n_tokens
#define ML 1024                 // max_length
#define NSEG (BB * NT)          // 3200
#define NCLS 5

// Output layout (concatenated f32): tokens [B,ML,C] | labels [B,ML] | pads [B,1]
#define TOK_ELEMS ((size_t)BB * ML * CC)   // 524288
#define LAB_OFF   TOK_ELEMS
#define PAD_OFF   (TOK_ELEMS + (size_t)BB * ML)

// Scratch: segment accumulators (1.6 MB, L2-resident) + class histograms
__device__ __align__(1024) float g_accum[NSEG * CC];
__device__ int g_hist[NSEG * NCLS];

// ---------------------------------------------------------------------------
// K1: zero accumulators + histograms
// ---------------------------------------------------------------------------
__global__ void k1_init() {
    int i = blockIdx.x * blockDim.x + threadIdx.x;
    if (i < NSEG * CC) g_accum[i] = 0.f;
    if (i < NSEG * NCLS) g_hist[i] = 0;
}

// ---------------------------------------------------------------------------
// K2: per-pixel class histogram (counts derived from hist later)
// ---------------------------------------------------------------------------
__global__ void k2_stats(const int* __restrict__ seg, const int* __restrict__ gts) {
    int n = BB * HWPX;
    for (int i = blockIdx.x * blockDim.x + threadIdx.x; i < n;
         i += gridDim.x * blockDim.x) {
        int b = i / HWPX;
        int s = seg[i] + b * NT;
        atomicAdd(&g_hist[s * NCLS + gts[i]], 1);
    }
}

// ---------------------------------------------------------------------------
// K3: main pass. Block = 32 pixels x 128 channels of one image.
//  stage1: coalesced LDG (channel-major) -> smem tile [c][p], pitch 33
//          STS lane-stride 1  -> conflict-free
//  stage2: lane l gathers channels {l, l+32, l+64, l+96} of pixel p
//          LDS bank = (33*(l+32j)+p) mod 32 = l  -> conflict-free
//          assembles permuted 512B pixel row in smem (STS.128, conflict-free)
//  reduce: TMA bulk-reduce (add.f32) of each 512B row into the segment's
//          L2-resident accumulator. No scalar atomics anywhere on the 512MB.
// Row position t holds channel (t&3)*32 + (t>>2); un-permuted in K4.
// ---------------------------------------------------------------------------
__global__ __launch_bounds__(256) void k3_main(const float* __restrict__ F,
                                               const int* __restrict__ seg) {
    __shared__ float tile[CC * 33];     // [c][p], pitch 33 (33,  *4B = 132B rows)
    __shared__ float rows[32 * CC];     // [p][pos]  512B per pixel row
    __shared__ int   sseg[32];

    int b  = blockIdx.y;
    int p0 = blockIdx.x * 32;
    int t  = threadIdx.x;
    int w  = t >> 5;
    int l  = t & 31;

    if (t < 32) sseg[t] = seg[b * HWPX + p0 + t] + b * NT;

    const float* Fb = F + (size_t)b * CC * HWPX + p0;
#pragma unroll
    for (int k = 0; k < 16; k++) {
        int c = (k << 3) + w;                       // covers channels 0..127
        tile[c * 33 + l] = Fb[(size_t)c * HWPX + l];
    }
    __syncthreads();

    // stage2: warp w owns pixels 4w .. 4w+3
#pragma unroll
    for (int i = 0; i < 4; i++) {
        int p = (w << 2) + i;
        float4 v;
        v.x = tile[(l      ) * 33 + p];
        v.y = tile[(l +  32) * 33 + p];
        v.z = tile[(l +  64) * 33 + p];
        v.w = tile[(l +  96) * 33 + p];
        *(float4*)&rows[p * CC + (l << 2)] = v;
    }
    __syncwarp();
    asm volatile("fence.proxy.async.shared::cta;" ::: "memory");

    if (l == 0) {
#pragma unroll
        for (int i = 0; i < 4; i++) {
            int p = (w << 2) + i;
            float* dst = g_accum + (size_t)sseg[p] * CC;
            uint32_t src = (uint32_t)__cvta_generic_to_shared(&rows[p * CC]);
            asm volatile(
                "cp.reduce.async.bulk.global.shared::cta.bulk_group.add.f32 "
                "[%0], [%1], %2;"
                :: "l"(dst), "r"(src), "r"(512) : "memory");
        }
        asm volatile("cp.async.bulk.commit_group;" ::: "memory");
        asm volatile("cp.async.bulk.wait_group 0;" ::: "memory");
    }
}

// ---------------------------------------------------------------------------
// K4: finalize. Block per (b, sl): mean (with channel un-permute), mode,
//     padding, pads. Tiny (reads 1.7 MB from L2, writes 2.1 MB).
// ---------------------------------------------------------------------------
__global__ __launch_bounds__(128) void k4_final(float* __restrict__ out) {
    int b  = blockIdx.y;
    int sl = blockIdx.x;
    int t  = threadIdx.x;

    float* tok = out + ((size_t)b * ML + sl) * CC;

    if (sl >= NT) {                       // padding region
        tok[t] = 0.f;
        if (t == 0) out[LAB_OFF + (size_t)b * ML + sl] = 0.f;
        return;
    }

    int s = b * NT + sl;

    // counts + mode from histogram
    __shared__ int s_cnt;
    if (t == 0) {
        int h[NCLS], cnt = 0;
#pragma unroll
        for (int c = 0; c < NCLS; c++) { h[c] = g_hist[s * NCLS + c]; cnt += h[c]; }
        int best = 0, bc = h[0];
#pragma unroll
        for (int c = 1; c < NCLS; c++) if (h[c] > bc) { bc = h[c]; best = c; }
        out[LAB_OFF + (size_t)b * ML + sl] = (float)best;
        if (sl == 0) out[PAD_OFF + b] = (float)(ML - NT);
        s_cnt = cnt;
    }
    __syncthreads();

    int cnt = s_cnt;
    float inv = 1.f / (float)(cnt > 0 ? cnt : 1);
    float v = g_accum[(size_t)s * CC + t] * inv;
    int c = ((t & 3) << 5) + (t >> 2);    // storage position -> true channel
    tok[c] = v;
}

// ---------------------------------------------------------------------------
extern "C" void kernel_launch(void* const* d_in, const int* in_sizes, int n_in,
                              void* d_out, int out_size) {
    const float* features = (const float*)d_in[0];
    const int*   gts      = (const int*)d_in[1];
    const int*   segments = (const int*)d_in[2];
    float*       out      = (float*)d_out;

    (void)in_sizes; (void)n_in; (void)out_size;

    k1_init<<<(NSEG * CC + 255) / 256, 256>>>();
    k2_stats<<<2048, 256>>>(segments, gts);
    {
        dim3 g(HWPX / 32, BB);            // (8192, 4)
        k3_main<<<g, 256>>>(features, segments);
    }
    {
        dim3 g(ML, BB);                   // (1024, 4)
        k4_final<<<g, 128>>>(out);
    }
}

// round 4
// speedup vs baseline: 2.9264x; 1.0080x over previous
#include <cuda_runtime.h>
#include <cuda_bf16.h>
#include <cstdint>

// Problem constants (fixed by setup_inputs)
#define BB 4
#define CC 128
#define HH 512
#define WW 512
#define HWPX (HH * WW)          // 262144 pixels per image
#define NT 800                  // n_tokens
#define ML 1024                 // max_length
#define NSEG (BB * NT)          // 3200
#define NCLS 5

// Output layout (concatenated f32): tokens [B,ML,C] | labels [B,ML] | pads [B,1]
#define TOK_ELEMS ((size_t)BB * ML * CC)   // 524288
#define LAB_OFF   TOK_ELEMS
#define PAD_OFF   (TOK_ELEMS + (size_t)BB * ML)

// Scratch: segment accumulators (1.6 MB, L2-resident) + class histograms
__device__ __align__(1024) float g_accum[NSEG * CC];
__device__ int g_hist[NSEG * NCLS];

// ---------------------------------------------------------------------------
// K1: zero accumulators + histograms
// ---------------------------------------------------------------------------
__global__ void k1_init() {
    int i = blockIdx.x * blockDim.x + threadIdx.x;
    if (i < NSEG * CC) g_accum[i] = 0.f;
    if (i < NSEG * NCLS) g_hist[i] = 0;
}

// ---------------------------------------------------------------------------
// K3: main pass (class histogram fused in). Block = 32 px x 128 ch, 256 thr.
//  stage1: coalesced scalar LDG (channel-major) -> smem tile [c][p], pitch 33
//          STS bank = (33c + l) % 32 = (c + l) % 32  -> conflict-free
//  stage2: lane l gathers channels {l,l+32,l+64,l+96} of pixel p
//          LDS bank = (33(l+32j) + p) % 32 = (l + p) % 32 -> conflict-free
//          builds permuted 512B pixel row (STS.128, phase-dense, no conflict)
//  reduce: TMA bulk-reduce add.f32 of each 512B row into the segment's
//          L2-resident accumulator. No scalar atomics on the 512 MB stream.
// Row position t holds channel (t&3)*32 + (t>>2); un-permuted in K4.
// ---------------------------------------------------------------------------
__global__ __launch_bounds__(256) void k3_main(const float* __restrict__ F,
                                               const int* __restrict__ seg,
                                               const int* __restrict__ gts,
                                               int b0) {
    __shared__ float tile[CC * 33];                     // [c][p] 16.9 KB
    __shared__ __align__(16) float rows[32 * CC];       // [p][pos] 16 KB
    __shared__ int sseg[32];

    int b  = b0 + blockIdx.y;
    int p0 = blockIdx.x * 32;
    int t  = threadIdx.x;
    int w  = t >> 5;
    int l  = t & 31;

    if (t < 32) {
        int gi = b * HWPX + p0 + t;
        int s  = seg[gi] + b * NT;
        sseg[t] = s;
        atomicAdd(&g_hist[s * NCLS + gts[gi]], 1);      // fused stats pass
    }

    const float* Fb = F + (size_t)b * CC * HWPX + p0;
#pragma unroll
    for (int k = 0; k < 16; k++) {
        int c = (k << 3) + w;                           // channels 0..127
        tile[c * 33 + l] = Fb[(size_t)c * HWPX + l];
    }
    __syncthreads();

    // stage2: warp w owns pixels 4w .. 4w+3
#pragma unroll
    for (int i = 0; i < 4; i++) {
        int p = (w << 2) + i;
        float4 v;
        v.x = tile[(l      ) * 33 + p];
        v.y = tile[(l +  32) * 33 + p];
        v.z = tile[(l +  64) * 33 + p];
        v.w = tile[(l +  96) * 33 + p];
        *(float4*)&rows[p * CC + (l << 2)] = v;
    }
    __syncwarp();
    asm volatile("fence.proxy.async.shared::cta;" ::: "memory");

    if (l == 0) {
#pragma unroll
        for (int i = 0; i < 4; i++) {
            int p = (w << 2) + i;
            float* dst = g_accum + (size_t)sseg[p] * CC;
            uint32_t src = (uint32_t)__cvta_generic_to_shared(&rows[p * CC]);
            asm volatile(
                "cp.reduce.async.bulk.global.shared::cta.bulk_group.add.f32 "
                "[%0], [%1], %2;"
                :: "l"(dst), "r"(src), "r"(512) : "memory");
        }
        asm volatile("cp.async.bulk.commit_group;" ::: "memory");
        asm volatile("cp.async.bulk.wait_group 0;" ::: "memory");
    }
}

// ---------------------------------------------------------------------------
// K4: finalize. Block per (b, sl): mean (with channel un-permute), mode,
//     padding, pads. Counts derived from the histogram.
// ---------------------------------------------------------------------------
__global__ __launch_bounds__(128) void k4_final(float* __restrict__ out) {
    int b  = blockIdx.y;
    int sl = blockIdx.x;
    int t  = threadIdx.x;

    float* tok = out + ((size_t)b * ML + sl) * CC;

    if (sl >= NT) {                       // padding region
        tok[t] = 0.f;
        if (t == 0) out[LAB_OFF + (size_t)b * ML + sl] = 0.f;
        return;
    }

    int s = b * NT + sl;

    __shared__ int s_cnt;
    if (t == 0) {
        int h[NCLS], cnt = 0;
#pragma unroll
        for (int c = 0; c < NCLS; c++) { h[c] = g_hist[s * NCLS + c]; cnt += h[c]; }
        int best = 0, bc = h[0];
#pragma unroll
        for (int c = 1; c < NCLS; c++) if (h[c] > bc) { bc = h[c]; best = c; }
        out[LAB_OFF + (size_t)b * ML + sl] = (float)best;
        if (sl == 0) out[PAD_OFF + b] = (float)(ML - NT);
        s_cnt = cnt;
    }
    __syncthreads();

    int cnt = s_cnt;
    float inv = 1.f / (float)(cnt > 0 ? cnt : 1);
    float v = g_accum[(size_t)s * CC + t] * inv;
    int c = ((t & 3) << 5) + (t >> 2);    // storage position -> true channel
    tok[c] = v;
}

// ---------------------------------------------------------------------------
extern "C" void kernel_launch(void* const* d_in, const int* in_sizes, int n_in,
                              void* d_out, int out_size) {
    const float* features = (const float*)d_in[0];
    const int*   gts      = (const int*)d_in[1];
    const int*   segments = (const int*)d_in[2];
    float*       out      = (float*)d_out;

    (void)in_sizes; (void)n_in; (void)out_size;

    k1_init<<<(NSEG * CC + 255) / 256, 256>>>();
    {
        dim3 g(HWPX / 32, 2);             // (8192, 2) per launch
        k3_main<<<g, 256>>>(features, segments, gts, 0);   // images 0,1
        k3_main<<<g, 256>>>(features, segments, gts, 2);   // images 2,3
    }
    {
        dim3 g(ML, BB);                   // (1024, 4)
        k4_final<<<g, 128>>>(out);
    }
}